// round 17
// baseline (speedup 1.0000x reference)
#include <cuda_runtime.h>
#include <cuda_fp16.h>

// Grid4D quadrilinear sample — L2-resident ping-pong tiles:
//  binning (stream 0): sort points by [u-tile][v_hi][x][y][v_mid][u_mid]
//  transpose stream: tile t (32 u-rows + halo) fp32 -> fp16 into buf[t%2]
//    (21.9 MB, L2-resident). T_{t+2} waits evG[t] (buffer free).
//  gather (stream 0): tile t points read buf[t%2] from L2; waits evT[t].
//  Overlap is DRAM (transpose) vs L2+LSU (gather) -> no DRAM contention.

#define RR 8
#define XX 9
#define YY 9
#define UU 512
#define VV 512
#define NS (XX * YY * UU * VV)
#define STR_R (NS)
#define STR_Y (UU * VV)

#define NBINS 65536
#define SCAN_BLOCKS 64
#define NCAP (1 << 20)
#define N_TILES 16
#define U_TILE 32
#define BUF_ROWS 33                       // 32 + 1 halo
#define BUF_CELLS (81 * BUF_ROWS * 512)   // 1,368,576 cells (21.9 MB fp16x8)
#define T_TILE_BLOCKS ((BUF_CELLS + 255) / 256)
#define GATHER_TILE_BLOCKS 592

__device__ uint4 g_buf[2][BUF_CELLS];     // 43.8 MB ping-pong, L2-resident
__device__ unsigned int g_binCnt[NBINS];
__device__ unsigned int g_binCursor[NBINS];
__device__ unsigned int g_blkSum[SCAN_BLOCKS];
__device__ unsigned int g_blkOff[SCAN_BLOCKS];
__device__ unsigned int g_tileStart[N_TILES + 1];
__device__ float4 g_pts[NCAP];
__device__ unsigned int g_oidx[NCAP];

__device__ __forceinline__ unsigned int h2_to_u32(__half2 v) {
    return *reinterpret_cast<unsigned int*>(&v);
}
__device__ __forceinline__ __half2 u32_to_h2(unsigned int v) {
    return *reinterpret_cast<__half2*>(&v);
}

// ---------------- tile transpose: grid fp32 -> buf fp16 ----------------
__global__ void __launch_bounds__(256)
transpose_tile_kernel(const float* __restrict__ grid, int tile, int parity) {
    int id = blockIdx.x * 256 + threadIdx.x;
    if (id >= BUF_CELLS) return;
    int v = id & 511;
    int rest = id >> 9;              // xy*33 + ul
    int ul = rest % BUF_ROWS;
    int xy = rest / BUF_ROWS;
    int u = (tile << 5) + ul;
    if (u >= UU) return;             // halo row past the grid (last tile)
    int s = xy * STR_Y + u * VV + v;
    uint4 packed;
    unsigned int* pu = &packed.x;
#pragma unroll
    for (int p = 0; p < 4; p++) {
        float a = __ldcs(grid + (2 * p + 0) * STR_R + s);   // read-once
        float b = __ldcs(grid + (2 * p + 1) * STR_R + s);
        pu[p] = h2_to_u32(__floats2half2_rn(a, b));
    }
    g_buf[parity][id] = packed;      // stays hot in L2
}

// ---------------- shared coordinate math ----------------
__device__ __forceinline__ void prep_dim(float c, float mn, float mx, int S,
                                         int& c0, int& dd, float& w0, float& w1) {
    float ind = (c - mn) / (mx - mn) * 2.0f - 1.0f;
    float pos = (ind + 1.0f) * 0.5f * (float)(S - 1);
    float fl = floorf(pos);
    int i0 = (int)fl;
    float f = pos - fl;
    w0 = 1.0f - f;
    w1 = f;
    if (i0 < 0 || i0 >= S) w0 = 0.0f;
    int i1 = i0 + 1;
    if (i1 < 0 || i1 >= S) w1 = 0.0f;
    int cc0 = min(max(i0, 0), S - 1);
    int cc1 = min(max(i1, 0), S - 1);
    c0 = cc0;
    dd = cc1 - cc0;
}

__device__ __forceinline__ int base_idx(float c, float mn, float mx, int S) {
    float ind = (c - mn) / (mx - mn) * 2.0f - 1.0f;
    float pos = (ind + 1.0f) * 0.5f * (float)(S - 1);
    int i0 = (int)floorf(pos);
    return min(max(i0, 0), S - 1);
}

// key = [tile:4][v_hi:3][x:3][y:3][v_mid:2][u_mid:1]  (16 bits)
__device__ __forceinline__ int compute_bin(float4 c, const float* mn4, const float* mx4) {
    int x0 = min(base_idx(c.x, mn4[0], mx4[0], XX), 7);
    int y0 = min(base_idx(c.y, mn4[1], mx4[1], YY), 7);
    int u0 = base_idx(c.z, mn4[2], mx4[2], UU);
    int v0 = base_idx(c.w, mn4[3], mx4[3], VV);
    int tile = u0 >> 5;
    int vh = v0 >> 6;
    int vm = (v0 >> 4) & 3;
    int um = (u0 >> 4) & 1;
    return (((((((((tile << 3) | vh) << 3) | x0) << 3) | y0) << 2) | vm) << 1) | um;
}

// ---------------- binning ----------------
__global__ void __launch_bounds__(1024)
zero_kernel() {
    int b = blockIdx.x * blockDim.x + threadIdx.x;
    if (b < NBINS) g_binCnt[b] = 0;
}

__global__ void __launch_bounds__(256)
hist_kernel(const float4* __restrict__ xyuv,
            const float* __restrict__ mn4, const float* __restrict__ mx4, int n) {
    int i = blockIdx.x * blockDim.x + threadIdx.x;
    if (i < n) atomicAdd(&g_binCnt[compute_bin(xyuv[i], mn4, mx4)], 1u);
}

__global__ void __launch_bounds__(1024)
scan_local_kernel() {
    __shared__ unsigned int s[1024];
    int t = threadIdx.x;
    int b = blockIdx.x * 1024 + t;
    unsigned int v = g_binCnt[b];
    s[t] = v;
    __syncthreads();
    for (int off = 1; off < 1024; off <<= 1) {
        unsigned int x = (t >= off) ? s[t - off] : 0u;
        __syncthreads();
        s[t] += x;
        __syncthreads();
    }
    g_binCursor[b] = s[t] - v;
    if (t == 1023) g_blkSum[blockIdx.x] = s[t];
}

__global__ void __launch_bounds__(SCAN_BLOCKS)
scan_top_kernel(int n) {
    __shared__ unsigned int s[SCAN_BLOCKS];
    int t = threadIdx.x;
    unsigned int v = g_blkSum[t];
    s[t] = v;
    __syncthreads();
    for (int off = 1; off < SCAN_BLOCKS; off <<= 1) {
        unsigned int x = (t >= off) ? s[t - off] : 0u;
        __syncthreads();
        s[t] += x;
        __syncthreads();
    }
    g_blkOff[t] = s[t] - v;
    if (t == 0) g_tileStart[N_TILES] = (unsigned int)n;
}

__global__ void __launch_bounds__(1024)
scan_add_kernel() {
    int b = blockIdx.x * 1024 + threadIdx.x;
    unsigned int val = g_binCursor[b] + g_blkOff[blockIdx.x];
    g_binCursor[b] = val;
    if ((b & 4095) == 0) g_tileStart[b >> 12] = val;   // 4096 bins per tile
}

__global__ void __launch_bounds__(256)
scatter_kernel(const float4* __restrict__ xyuv,
               const float* __restrict__ mn4, const float* __restrict__ mx4, int n) {
    int i = blockIdx.x * blockDim.x + threadIdx.x;
    if (i >= n) return;
    float4 c = xyuv[i];
    int bin = compute_bin(c, mn4, mx4);
    unsigned int pos = atomicAdd(&g_binCursor[bin], 1u);
    g_pts[pos] = c;
    g_oidx[pos] = (unsigned int)i;
}

// ---------------- per-tile gather (reads L2-resident buffer) ----------------
__global__ void __launch_bounds__(256)
gather_tile_kernel(const float* __restrict__ mn4,
                   const float* __restrict__ mx4,
                   float* __restrict__ out, int tile, int parity) {
    unsigned int start = g_tileStart[tile];
    unsigned int end   = g_tileStart[tile + 1];
    const uint4* __restrict__ buf = g_buf[parity];
    int ubase = tile << 5;

    for (unsigned int t = start + blockIdx.x * blockDim.x + threadIdx.x;
         t < end; t += (unsigned int)gridDim.x * blockDim.x) {
        float4 c = __ldcs(&g_pts[t]);

        int x0, y0, u0, v0, dx, dy, du, dv;
        float wx0, wx1, wy0, wy1, wu0, wu1, wv0, wv1;
        prep_dim(c.x, mn4[0], mx4[0], XX, x0, dx, wx0, wx1);
        prep_dim(c.y, mn4[1], mx4[1], YY, y0, dy, wy0, wy1);
        prep_dim(c.z, mn4[2], mx4[2], UU, u0, du, wu0, wu1);
        prep_dim(c.w, mn4[3], mx4[3], VV, v0, dv, wv0, wv1);

        int ul0 = u0 - ubase;          // [0, 32)

        int sidx[8];
        float w[8];
#pragma unroll
        for (int k = 0; k < 8; k++) {
            int xa = (k >> 2) & 1;
            int ya = (k >> 1) & 1;
            int ua = k & 1;
            int xi = x0 + (xa ? dx : 0);
            int yi = y0 + (ya ? dy : 0);
            int ul = ul0 + (ua ? du : 0);       // [0, 32]
            sidx[k] = ((xi * YY + yi) * BUF_ROWS + ul) * 512 + v0;
            w[k] = (xa ? wx1 : wx0) * (ya ? wy1 : wy0) * (ua ? wu1 : wu0);
        }

        float acc[RR];
#pragma unroll
        for (int r = 0; r < RR; r++) acc[r] = 0.0f;

#pragma unroll 2
        for (int k = 0; k < 8; k++) {
            int s0 = sidx[k];
            uint4 A = buf[s0];
            uint4 B = buf[s0 + dv];
            float wa = w[k] * wv0;
            float wb = w[k] * wv1;
            const unsigned int* au = &A.x;
            const unsigned int* bu = &B.x;
#pragma unroll
            for (int p = 0; p < 4; p++) {
                float2 fa = __half22float2(u32_to_h2(au[p]));
                float2 fb = __half22float2(u32_to_h2(bu[p]));
                acc[2 * p + 0] = fmaf(wa, fa.x, fmaf(wb, fb.x, acc[2 * p + 0]));
                acc[2 * p + 1] = fmaf(wa, fa.y, fmaf(wb, fb.y, acc[2 * p + 1]));
            }
        }

        unsigned int oi = __ldcs(&g_oidx[t]);
        float4* o4 = reinterpret_cast<float4*>(out + (size_t)oi * RR);
        __stcs(&o4[0], make_float4(acc[0], acc[1], acc[2], acc[3]));
        __stcs(&o4[1], make_float4(acc[4], acc[5], acc[6], acc[7]));
    }
}

extern "C" void kernel_launch(void* const* d_in, const int* in_sizes, int n_in,
                              void* d_out, int out_size) {
    const float4* xyuv = (const float4*)d_in[0];
    const float* grid  = (const float*)d_in[1];
    const float* mn4   = (const float*)d_in[2];
    const float* mx4   = (const float*)d_in[3];
    float* out = (float*)d_out;

    int n = in_sizes[0] / 4;  // 1,048,576 points
    if (n > NCAP) n = NCAP;

    static cudaStream_t sA = nullptr;
    static cudaEvent_t evFork = nullptr;
    static cudaEvent_t evT[N_TILES], evG[N_TILES];
    if (!sA) {
        cudaStreamCreateWithFlags(&sA, cudaStreamNonBlocking);
        cudaEventCreateWithFlags(&evFork, cudaEventDisableTiming);
        for (int t = 0; t < N_TILES; t++) {
            cudaEventCreateWithFlags(&evT[t], cudaEventDisableTiming);
            cudaEventCreateWithFlags(&evG[t], cudaEventDisableTiming);
        }
    }

    int pBlocks = (n + 255) / 256;

    // Fork; first two transposes fill both buffers while binning runs.
    cudaEventRecord(evFork, 0);
    cudaStreamWaitEvent(sA, evFork, 0);
    transpose_tile_kernel<<<T_TILE_BLOCKS, 256, 0, sA>>>(grid, 0, 0);
    cudaEventRecord(evT[0], sA);
    transpose_tile_kernel<<<T_TILE_BLOCKS, 256, 0, sA>>>(grid, 1, 1);
    cudaEventRecord(evT[1], sA);

    // Binning chain on stream 0.
    zero_kernel<<<NBINS / 1024, 1024>>>();
    hist_kernel<<<pBlocks, 256>>>(xyuv, mn4, mx4, n);
    scan_local_kernel<<<SCAN_BLOCKS, 1024>>>();
    scan_top_kernel<<<1, SCAN_BLOCKS>>>(n);
    scan_add_kernel<<<SCAN_BLOCKS, 1024>>>();
    scatter_kernel<<<pBlocks, 256>>>(xyuv, mn4, mx4, n);

    // Pipelined gathers; T_{t+2} launches after G_t frees its buffer.
    for (int t = 0; t < N_TILES; t++) {
        cudaStreamWaitEvent(0, evT[t], 0);
        gather_tile_kernel<<<GATHER_TILE_BLOCKS, 256>>>(mn4, mx4, out, t, t & 1);
        cudaEventRecord(evG[t], 0);
        if (t + 2 < N_TILES) {
            cudaStreamWaitEvent(sA, evG[t], 0);
            transpose_tile_kernel<<<T_TILE_BLOCKS, 256, 0, sA>>>(grid, t + 2, (t + 2) & 1);
            cudaEventRecord(evT[t + 2], sA);
        }
    }
}